// round 13
// baseline (speedup 1.0000x reference)
#include <cuda_runtime.h>
#include <math.h>

#define Bb   2
#define Nn   1024
#define DIMM 1024
#define Hh   8
#define DHh  64
#define DIi  512
#define BN   (Bb*Nn)
#define NC   16          // chunks per (b,h)
#define CS   64          // chunk size

static __device__ __constant__ float EPSf = 1.1920929e-07f;

// ---------------- scratch ----------------
__device__ float g_xa[BN*DIMM];
__device__ float g_qp[BN*DIi];
__device__ float g_kp[BN*DIi];
__device__ float g_vp[BN*DIi];
__device__ float g_y [BN*DIi];
__device__ float g_ga[BN*24];
__device__ float g_gz[256*4096];
__device__ float g_gs[256*4096];
__device__ float g_sc[256*128];
__device__ float g_sc2[256*4];

// ---------------- tf32 helpers ----------------
__device__ __forceinline__ unsigned f2tf(float f) {
    unsigned r; asm("cvt.rna.tf32.f32 %0, %1;" : "=r"(r) : "f"(f)); return r;
}
__device__ __forceinline__ uint4 tf4(float4 v) {
    return make_uint4(f2tf(v.x), f2tf(v.y), f2tf(v.z), f2tf(v.w));
}
__device__ __forceinline__ void mma_tf32(float* c, const unsigned* a, const unsigned* b) {
    asm volatile(
        "mma.sync.aligned.m16n8k8.row.col.f32.tf32.tf32.f32 "
        "{%0,%1,%2,%3}, {%4,%5,%6,%7}, {%8,%9}, {%0,%1,%2,%3};"
        : "+f"(c[0]), "+f"(c[1]), "+f"(c[2]), "+f"(c[3])
        : "r"(a[0]), "r"(a[1]), "r"(a[2]), "r"(a[3]), "r"(b[0]), "r"(b[1]));
}

// ---------------- 1. RMSNorm ----------------
__global__ void k_rmsnorm(const float* __restrict__ x, const float* __restrict__ w) {
    int row = blockIdx.x;
    int tid = threadIdx.x;
    const float4* xr = (const float4*)(x + (size_t)row * DIMM);
    float4 xv = xr[tid];
    float ss = xv.x*xv.x + xv.y*xv.y + xv.z*xv.z + xv.w*xv.w;
    #pragma unroll
    for (int o = 16; o > 0; o >>= 1) ss += __shfl_xor_sync(0xffffffffu, ss, o);
    __shared__ float sred[8];
    if ((tid & 31) == 0) sred[tid >> 5] = ss;
    __syncthreads();
    float tot = 0.f;
    #pragma unroll
    for (int i = 0; i < 8; i++) tot += sred[i];
    float inv = rsqrtf(tot * (1.0f / DIMM) + EPSf);
    float4 wv = ((const float4*)w)[tid];
    float4 o;
    o.x = xv.x * inv * wv.x; o.y = xv.y * inv * wv.y;
    o.z = xv.z * inv * wv.z; o.w = xv.w * inv * wv.w;
    ((float4*)g_xa)[(size_t)row * (DIMM/4) + tid] = o;
}

// ---------------- gates body (runs inside k_gemm3's shadow) ----------------
__device__ void gates_body(const float* __restrict__ lw, const float* __restrict__ dw,
                           const float* __restrict__ mw, int gb, void* smraw) {
    float* As = (float*)smraw;            // [64][20]
    float* Ws = (float*)smraw + 64*20;    // [16][24]
    int tid = threadIdx.x;
    int hh = tid & 7, ty = tid >> 3;
    int row0 = gb * 64;
    float acc[2][3] = {};
    for (int k0 = 0; k0 < DIMM; k0 += 16) {
        {
            int mm = tid >> 2, kq = (tid & 3) * 4;
            float4 v = *(const float4*)(g_xa + (size_t)(row0+mm)*DIMM + k0 + kq);
            As[mm*20+kq+0]=v.x; As[mm*20+kq+1]=v.y; As[mm*20+kq+2]=v.z; As[mm*20+kq+3]=v.w;
        }
        if (tid < 128) {
            int kk = tid >> 3, h2 = tid & 7;
            Ws[kk*24+h2]    = lw[(k0+kk)*Hh + h2];
            Ws[kk*24+8+h2]  = dw[(k0+kk)*Hh + h2];
            Ws[kk*24+16+h2] = mw[(k0+kk)*Hh + h2];
        }
        __syncthreads();
        #pragma unroll
        for (int kk = 0; kk < 16; kk++) {
            float a0 = As[(ty*2)*20+kk], a1 = As[(ty*2+1)*20+kk];
            float w0 = Ws[kk*24+hh], w1 = Ws[kk*24+8+hh], w2 = Ws[kk*24+16+hh];
            acc[0][0] += a0*w0; acc[0][1] += a0*w1; acc[0][2] += a0*w2;
            acc[1][0] += a1*w0; acc[1][1] += a1*w1; acc[1][2] += a1*w2;
        }
        __syncthreads();
    }
    #pragma unroll
    for (int i = 0; i < 2; i++) {
        int row = row0 + ty*2 + i;
        g_ga[row*24 + hh]      = acc[i][0];
        g_ga[row*24 + 8 + hh]  = acc[i][1];
        g_ga[row*24 + 16 + hh] = acc[i][2];
    }
}

// ---------------- 2. tf32 GEMM core: double-buffered smem -----------------
template<bool FC, int MI, int WCN>
__device__ __forceinline__ void gemm_tc(const float* __restrict__ A,
                                        const float* __restrict__ Bm,
                                        float* __restrict__ C,
                                        int Nc, int Kc,
                                        const float* __restrict__ cw) {
    extern __shared__ unsigned smem[];
    unsigned* As = smem;                  // [2][4*520]
    unsigned* Bs = smem + 2*2080;         // [2][WCN*8*128]
    const int BSW = WCN*8*128;
    int tid = threadIdx.x;
    int lane = tid & 31, wid = tid >> 5;
    int wr = wid / WCN, wc = wid % WCN;
    int gid = lane >> 2, tig = lane & 3;
    int row0 = blockIdx.y * 128, col0 = blockIdx.x * (WCN*64);

    int ar = tid >> 1;
    int kqb = (tid & 1) * 2;
    int bk = lane >> 1, bq = lane & 1;

    int m = row0 + ar;
    int tloc = 0, b0 = 0;
    if (FC) { b0 = m & ~(Nn - 1); tloc = m - b0; }

    float acc[MI][8][4];
    #pragma unroll
    for (int i = 0; i < MI; i++)
        #pragma unroll
        for (int j = 0; j < 8; j++)
            #pragma unroll
            for (int q = 0; q < 4; q++) acc[i][j][q] = 0.f;

    float4 ra[2], rb[WCN];
    const float4* A4 = (const float4*)A;
    const float4* B4 = (const float4*)Bm;
    const float4* XA4 = (const float4*)g_xa;
    const float4* CW4 = (const float4*)cw;

    #define PREFETCH(kn)                                                        \
    {                                                                           \
        _Pragma("unroll")                                                       \
        for (int p = 0; p < 2; p++) {                                           \
            int kq = kqb + p;                                                   \
            if (!FC) {                                                          \
                ra[p] = A4[(size_t)m * (Kc >> 2) + ((kn) >> 2) + kq];           \
            } else {                                                            \
                int kb = (kn) + kq * 4;                                         \
                float we[4][4];                                                 \
                _Pragma("unroll")                                               \
                for (int e = 0; e < 4; e++) *(float4*)we[e] = CW4[kb + e];      \
                float4 r = make_float4(0.f, 0.f, 0.f, 0.f);                     \
                _Pragma("unroll")                                               \
                for (int j = 0; j < 4; j++) {                                   \
                    int tl = tloc + j - 2;                                      \
                    if ((unsigned)tl < (unsigned)Nn) {                          \
                        float4 xv = XA4[(size_t)(b0 + tl) * (DIMM >> 2) + (kb >> 2)]; \
                        r.x += xv.x * we[0][j]; r.y += xv.y * we[1][j];         \
                        r.z += xv.z * we[2][j]; r.w += xv.w * we[3][j];         \
                    }                                                           \
                }                                                               \
                ra[p] = r;                                                      \
            }                                                                   \
        }                                                                       \
        _Pragma("unroll")                                                       \
        for (int p = 0; p < WCN; p++) {                                         \
            int nt = wid + p * 8;                                               \
            rb[p] = B4[(size_t)((kn) + bk) * (Nc >> 2) + (col0 >> 2) + nt * 2 + bq]; \
        }                                                                       \
    }

    #define STORE(buf)                                                          \
    {                                                                           \
        unsigned* Aw = As + (buf)*2080;                                         \
        unsigned* Bw = Bs + (buf)*BSW;                                          \
        _Pragma("unroll")                                                       \
        for (int p = 0; p < 2; p++)                                             \
            *(uint4*)&Aw[(kqb+p)*520 + ar*4] = tf4(ra[p]);                      \
        _Pragma("unroll")                                                       \
        for (int p = 0; p < WCN; p++) {                                         \
            int nt = wid + p * 8;                                               \
            *(uint4*)&Bw[nt*128 + bk*8 + bq*4] = tf4(rb[p]);                    \
        }                                                                       \
    }

    PREFETCH(0)
    STORE(0)
    __syncthreads();

    for (int k0 = 0; k0 < Kc; k0 += 16) {
        int cur = (k0 >> 4) & 1;
        bool more = (k0 + 16 < Kc);
        if (more) PREFETCH(k0 + 16)
        const unsigned* Abuf = As + cur*2080;
        const unsigned* Bbuf = Bs + cur*BSW;
        #pragma unroll
        for (int c = 0; c < 2; c++) {
            unsigned a[MI][4];
            const unsigned* s0 = Abuf + (c*2)*520;
            const unsigned* s1 = Abuf + (c*2+1)*520;
            #pragma unroll
            for (int mi = 0; mi < MI; mi++) {
                int m0 = (wr*MI + mi) * 16;
                a[mi][0] = s0[(m0+gid)*4 + tig];
                a[mi][1] = s0[(m0+gid+8)*4 + tig];
                a[mi][2] = s1[(m0+gid)*4 + tig];
                a[mi][3] = s1[(m0+gid+8)*4 + tig];
            }
            #pragma unroll
            for (int ni = 0; ni < 8; ni++) {
                int nt = wc*8 + ni;
                unsigned b[2];
                b[0] = Bbuf[nt*128 + (c*8+tig)*8 + gid];
                b[1] = Bbuf[nt*128 + (c*8+tig+4)*8 + gid];
                #pragma unroll
                for (int mi = 0; mi < MI; mi++) mma_tf32(acc[mi][ni], a[mi], b);
            }
        }
        if (more) {
            STORE(cur ^ 1)
            __syncthreads();
        }
    }
    #undef PREFETCH
    #undef STORE

    #pragma unroll
    for (int mi = 0; mi < MI; mi++) {
        #pragma unroll
        for (int ni = 0; ni < 8; ni++) {
            int row = row0 + (wr*MI + mi)*16 + gid;
            int col = col0 + (wc*8 + ni)*8 + tig*2;
            *(float2*)(C + (size_t)row * Nc + col) =
                make_float2(acc[mi][ni][0], acc[mi][ni][1]);
            *(float2*)(C + (size_t)(row+8) * Nc + col) =
                make_float2(acc[mi][ni][2], acc[mi][ni][3]);
        }
    }
}

// z<3: QKV GEMM tiles; z==3: gate projections (fills idle SMs of the wave)
__global__ __launch_bounds__(256, 1)
void k_gemm3(const float* __restrict__ B0, const float* __restrict__ B1,
             const float* __restrict__ B2,
             const float* __restrict__ cw0, const float* __restrict__ cw1,
             const float* __restrict__ cw2,
             const float* __restrict__ lw, const float* __restrict__ dw,
             const float* __restrict__ mw,
             float* __restrict__ C0, float* __restrict__ C1,
             float* __restrict__ C2) {
    if (blockIdx.z < 3) {
        const float* Bm = (blockIdx.z == 0) ? B0 : ((blockIdx.z == 1) ? B1 : B2);
        const float* cw = (blockIdx.z == 0) ? cw0 : ((blockIdx.z == 1) ? cw1 : cw2);
        float* C = (blockIdx.z == 0) ? C0 : ((blockIdx.z == 1) ? C1 : C2);
        gemm_tc<true, 4, 4>(nullptr, Bm, C, DIi, DIMM, cw);
    } else {
        extern __shared__ unsigned smraw[];
        int gb = blockIdx.y * 2 + blockIdx.x;   // 0..31
        gates_body(lw, dw, mw, gb, (void*)smraw);
    }
}

__global__ __launch_bounds__(256, 1)
void k_gemm1(const float* __restrict__ A, const float* __restrict__ Bm,
             float* __restrict__ C, int Nc, int Kc) {
    gemm_tc<false, 2, 2>(A, Bm, C, Nc, Kc, nullptr);
}

// ---------------- 4a. chunk kernel A (+ fused per-head RMSNorm) -----------
__global__ __launch_bounds__(256, 1)
void k_chunkA(const float* __restrict__ lb, const float* __restrict__ db,
              const float* __restrict__ mb,
              const float* __restrict__ gq, const float* __restrict__ gk) {
    extern __shared__ float sm[];
    float* sq  = sm;            // 64x65, reused as T
    float* sk  = sm + 4160;
    float* sv  = sm + 8320;
    float* sE  = sm + 12480;
    float* slr = sm + 16640;
    float* sde = sm + 16704;
    float* smo = sm + 16768;
    float* sAe = sm + 16832;
    float* sEe = sm + 16896;
    float* ssc = sm + 16960;
    float* ssc2= sm + 17088;

    int tid = threadIdx.x;
    int cc = blockIdx.x;
    int bh = cc >> 4, c = cc & 15;
    int b = bh >> 3, h = bh & 7;
    int t0 = c * CS;
    const size_t base = (size_t)b * Nn * DIi + h * DHh;

    {
        int f4 = tid & 15, r0 = tid >> 4;
        #pragma unroll
        for (int rr = 0; rr < 4; rr++) {
            int row = rr*16 + r0;
            size_t g = base + (size_t)(t0+row)*DIi + f4*4;
            float4 vq = *(const float4*)(g_qp + g);
            float4 vk = *(const float4*)(g_kp + g);
            float4 vv = *(const float4*)(g_vp + g);
            int so = row*65 + f4*4;
            sq[so]=vq.x; sq[so+1]=vq.y; sq[so+2]=vq.z; sq[so+3]=vq.w;
            sk[so]=vk.x; sk[so+1]=vk.y; sk[so+2]=vk.z; sk[so+3]=vk.w;
            sv[so]=vv.x; sv[so+1]=vv.y; sv[so+2]=vv.z; sv[so+3]=vv.w;
        }
    }
    if (tid < 192) {
        int i = tid / 3, gi = tid - i*3;
        const float* bb = (gi==0) ? lb : ((gi==1) ? db : mb);
        float raw = g_ga[(size_t)(b*Nn + t0 + i)*24 + gi*8 + h] + bb[h];
        float v = 1.f/(1.f+__expf(-raw));
        ((gi==0) ? slr : ((gi==1) ? sde : smo))[i] = v;
    }
    __syncthreads();

    {
        int row = tid >> 2, seg = (tid & 3) * 16;
        float ssq = 0.f, ssk = 0.f;
        #pragma unroll
        for (int j = 0; j < 16; j++) {
            float a = sq[row*65 + seg + j]; ssq += a*a;
            float e = sk[row*65 + seg + j]; ssk += e*e;
        }
        ssq += __shfl_xor_sync(0xffffffffu, ssq, 1);
        ssq += __shfl_xor_sync(0xffffffffu, ssq, 2);
        ssk += __shfl_xor_sync(0xffffffffu, ssk, 1);
        ssk += __shfl_xor_sync(0xffffffffu, ssk, 2);
        float invq = 1.f / fmaxf(sqrtf(ssq) * 0.125f, 1e-8f);
        float invk = 1.f / fmaxf(sqrtf(ssk) * 0.125f, 1e-8f);
        float qb[16];
        #pragma unroll
        for (int j = 0; j < 16; j++) {
            float nq = sq[row*65 + seg + j] * invq * gq[h*DHh + seg + j];
            sq[row*65 + seg + j] = nq; qb[j] = nq;
            sk[row*65 + seg + j] = sk[row*65 + seg + j] * invk * gk[h*DHh + seg + j];
        }
        #pragma unroll
        for (int j = 0; j < 4; j++)
            *(float4*)(g_qp + base + (size_t)(t0+row)*DIi + seg + j*4) =
                make_float4(qb[j*4], qb[j*4+1], qb[j*4+2], qb[j*4+3]);
    }
    if (tid < 64) {
        int u = tid;
        float A_=0.f, E_=0.f, Amul=1.f, Dmul=1.f, F=0.f;
        for (int i = 0; i < 64; i++) {
            sE[i*65 + u] = E_;
            if (u == i) { ssc[i*2] = Dmul; ssc[i*2+1] = F; }
            float ai = smo[i], di = sde[i], li = slr[i];
            A_ = ai * A_; if (u == i) A_ = 1.f;
            E_ = di * E_ + li * A_;
            Amul *= ai; F = di * F + li * Amul; Dmul *= di;
        }
        sAe[u] = A_; sEe[u] = E_;
        if (u == 0) { ssc2[0] = Amul; ssc2[1] = Dmul; ssc2[2] = F; }
    }
    __syncthreads();

    int tx = tid & 15, ty = tid >> 4;
    float a1[4][4];
    #pragma unroll
    for (int i = 0; i < 4; i++)
        #pragma unroll
        for (int j = 0; j < 4; j++) a1[i][j] = 0.f;
    for (int p = 0; p < 64; p++) {
        float aa[4], bb[4];
        #pragma unroll
        for (int j = 0; j < 4; j++) aa[j] = sq[(ty*4+j)*65 + p];
        #pragma unroll
        for (int j = 0; j < 4; j++) bb[j] = sk[(tx*4+j)*65 + p];
        #pragma unroll
        for (int i = 0; i < 4; i++)
            #pragma unroll
            for (int j = 0; j < 4; j++) a1[i][j] += aa[i]*bb[j];
    }
    __syncthreads();
    #pragma unroll
    for (int i = 0; i < 4; i++)
        #pragma unroll
        for (int j = 0; j < 4; j++)
            sq[(ty*4+i)*65 + tx*4+j] = a1[i][j] * sE[(ty*4+i)*65 + tx*4+j];
    __syncthreads();

    float a2[4][4];
    #pragma unroll
    for (int i = 0; i < 4; i++)
        #pragma unroll
        for (int j = 0; j < 4; j++) a2[i][j] = 0.f;
    for (int u = 0; u < 64; u++) {
        float aa[4], bb[4];
        #pragma unroll
        for (int j = 0; j < 4; j++) aa[j] = sq[(ty*4+j)*65 + u];
        #pragma unroll
        for (int j = 0; j < 4; j++) bb[j] = sv[u*65 + tx*4+j];
        #pragma unroll
        for (int i = 0; i < 4; i++)
            #pragma unroll
            for (int j = 0; j < 4; j++) a2[i][j] += aa[i]*bb[j];
    }
    #pragma unroll
    for (int i = 0; i < 4; i++)
        *(float4*)(g_y + base + (size_t)(t0 + ty*4+i)*DIi + tx*4) =
            make_float4(a2[i][0], a2[i][1], a2[i][2], a2[i][3]);

    float az[4][4], as_[4][4];
    #pragma unroll
    for (int i = 0; i < 4; i++)
        #pragma unroll
        for (int j = 0; j < 4; j++) { az[i][j]=0.f; as_[i][j]=0.f; }
    for (int u = 0; u < 64; u++) {
        float wz = sAe[u], ws = sEe[u];
        float aa[4], bb[4];
        #pragma unroll
        for (int j = 0; j < 4; j++) aa[j] = sv[u*65 + ty*4+j];
        #pragma unroll
        for (int j = 0; j < 4; j++) bb[j] = sk[u*65 + tx*4+j];
        #pragma unroll
        for (int i = 0; i < 4; i++) {
            float azw = wz*aa[i], asw = ws*aa[i];
            #pragma unroll
            for (int j = 0; j < 4; j++) { az[i][j] += azw*bb[j]; as_[i][j] += asw*bb[j]; }
        }
    }
    #pragma unroll
    for (int i = 0; i < 4; i++) {
        size_t go = (size_t)cc*4096 + (ty*4+i)*64 + tx*4;
        *(float4*)(g_gz + go) = make_float4(az[i][0], az[i][1], az[i][2], az[i][3]);
        *(float4*)(g_gs + go) = make_float4(as_[i][0], as_[i][1], as_[i][2], as_[i][3]);
    }
    if (tid < 128) g_sc[(size_t)cc*128 + tid] = ssc[tid];
    if (tid >= 128 && tid < 131) g_sc2[(size_t)cc*4 + (tid-128)] = ssc2[tid-128];
}

// ---------------- 4b. chunk kernel B: single-barrier double-buffered ------
__global__ __launch_bounds__(256, 1)
void k_chunkB() {
    extern __shared__ float smB[];
    float* sQ  = smB;               // [2][64*65]
    float* sS  = smB + 8320;        // [2][16*65]
    float* sZ  = smB + 12480;       // [2][16*65]
    float* ssc = smB + 16640;       // [2][128]
    float* ssc2= smB + 16896;       // [2][4]

    int tid = threadIdx.x;
    int bh = blockIdx.x >> 2, rb_ = blockIdx.x & 3;
    int b = bh >> 3, h = bh & 7;
    int rg = rb_ * 16;
    const size_t base = (size_t)b * Nn * DIi + h * DHh;
    int lane = tid & 31, wid = tid >> 5;
    int wm = wid & 3, wn = wid >> 2;
    int g = lane >> 2, t4 = lane & 3;
    int f4 = tid & 15, r0q = tid >> 4;
    int cidx = tid * 4;
    int crow = cidx >> 6, ccol = cidx & 63;

    for (int i = tid; i < 16*65; i += 256) { sS[i] = 0.f; sZ[i] = 0.f; }
    // load chunk-0 Q/scalars into buffer 0
    {
        #pragma unroll
        for (int rr = 0; rr < 4; rr++) {
            float4 v = *(const float4*)(g_qp + base + (size_t)(rr*16 + r0q)*DIi + f4*4);
            int so = (rr*16 + r0q)*65 + f4*4;
            sQ[so]=v.x; sQ[so+1]=v.y; sQ[so+2]=v.z; sQ[so+3]=v.w;
        }
        if (tid < 128) ssc[tid] = g_sc[(size_t)(bh*16)*128 + tid];
        if (tid < 4)   ssc2[tid] = g_sc2[(size_t)(bh*16)*4 + tid];
    }
    __syncthreads();

    for (int c = 0; c < NC; c++) {
        int qb = c & 1;
        int cc = bh*16 + c, t0 = c * CS;
        const float* Qc = sQ + qb*4160;
        const float* Sc = sS + qb*1040;
        const float* Zc = sZ + qb*1040;
        float* Sn = sS + (qb^1)*1040;
        float* Zn = sZ + (qb^1)*1040;

        // ---- prefetch everything global this chunk needs (issued early) ----
        int i0 = wm*16 + g;
        int rr = rg + wn*8 + 2*t4;
        float* py0 = g_y + base + (size_t)(t0+i0)*DIi + rr;
        float* py1 = g_y + base + (size_t)(t0+i0+8)*DIi + rr;
        float2 e0 = *(float2*)py0, e1 = *(float2*)py1;
        size_t go = (size_t)cc*4096 + (rg+crow)*64 + ccol;
        float4 rgz = *(const float4*)(g_gz + go);
        float4 rgs = *(const float4*)(g_gs + go);
        float4 rq[4];
        float rsc = 0.f, rsc2v = 0.f;
        bool hasnext = (c + 1 < NC);
        if (hasnext) {
            int tn = t0 + CS;
            #pragma unroll
            for (int r4 = 0; r4 < 4; r4++)
                rq[r4] = *(const float4*)(g_qp + base + (size_t)(tn + r4*16 + r0q)*DIi + f4*4);
            if (tid < 128) rsc  = g_sc[(size_t)(cc+1)*128 + tid];
            if (tid < 4)   rsc2v = g_sc2[(size_t)(cc+1)*4 + tid];
        }

        // ---- mma: Y1 = Q S^T, Y2 = Q Z^T (reads buffers 'cur' only) ----
        float y1[4] = {0.f,0.f,0.f,0.f}, y2[4] = {0.f,0.f,0.f,0.f};
        #pragma unroll
        for (int k0 = 0; k0 < 64; k0 += 8) {
            unsigned a[4], bs[2], bz[2];
            a[0] = f2tf(Qc[(wm*16+g)*65   + k0+t4]);
            a[1] = f2tf(Qc[(wm*16+g+8)*65 + k0+t4]);
            a[2] = f2tf(Qc[(wm*16+g)*65   + k0+t4+4]);
            a[3] = f2tf(Qc[(wm*16+g+8)*65 + k0+t4+4]);
            bs[0] = f2tf(Sc[(wn*8+g)*65 + k0+t4]);
            bs[1] = f2tf(Sc[(wn*8+g)*65 + k0+t4+4]);
            bz[0] = f2tf(Zc[(wn*8+g)*65 + k0+t4]);
            bz[1] = f2tf(Zc[(wn*8+g)*65 + k0+t4+4]);
            mma_tf32(y1, a, bs);
            mma_tf32(y2, a, bz);
        }
        // y RMW (stores issued pre-barrier; loads were prefetched)
        {
            float dm0 = ssc[qb*128 + i0*2],     f0 = ssc[qb*128 + i0*2+1];
            float dm1 = ssc[qb*128 + (i0+8)*2], f1 = ssc[qb*128 + (i0+8)*2+1];
            e0.x += dm0*y1[0] - f0*y2[0]; e0.y += dm0*y1[1] - f0*y2[1];
            e1.x += dm1*y1[2] - f1*y2[2]; e1.y += dm1*y1[3] - f1*y2[3];
            *(float2*)py0 = e0; *(float2*)py1 = e1;
        }
        // carry update: read cur, write next buffer (no race with mma readers)
        {
            float ame = ssc2[qb*4+0], dme = ssc2[qb*4+1], fe = ssc2[qb*4+2];
            const float* ps = Sc + crow*65 + ccol;
            const float* pz = Zc + crow*65 + ccol;
            float* qs = Sn + crow*65 + ccol;
            float* qz = Zn + crow*65 + ccol;
            float s0=ps[0], s1=ps[1], s2=ps[2], s3=ps[3];
            float z0=pz[0], z1=pz[1], z2=pz[2], z3=pz[3];
            qs[0] = dme*s0 - fe*z0 + rgs.x; qz[0] = ame*z0 - rgz.x;
            qs[1] = dme*s1 - fe*z1 + rgs.y; qz[1] = ame*z1 - rgz.y;
            qs[2] = dme*s2 - fe*z2 + rgs.z; qz[2] = ame*z2 - rgz.z;
            qs[3] = dme*s3 - fe*z3 + rgs.w; qz[3] = ame*z3 - rgz.w;
        }
        // next-chunk Q/scalars into the other buffer
        if (hasnext) {
            float* Qn = sQ + (qb^1)*4160;
            #pragma unroll
            for (int r4 = 0; r4 < 4; r4++) {
                int so = (r4*16 + r0q)*65 + f4*4;
                Qn[so]=rq[r4].x; Qn[so+1]=rq[r4].y; Qn[so+2]=rq[r4].z; Qn[so+3]=rq[r4].w;
            }
            if (tid < 128) ssc[(qb^1)*128 + tid] = rsc;
            if (tid < 4)   ssc2[(qb^1)*4 + tid] = rsc2v;
        }
        __syncthreads();   // single barrier per chunk
    }
}

// ---------------- launch ----------------
extern "C" void kernel_launch(void* const* d_in, const int* in_sizes, int n_in,
                              void* d_out, int out_size) {
    const float* x      = (const float*)d_in[0];
    const float* w_rms  = (const float*)d_in[1];
    const float* wq     = (const float*)d_in[2];
    const float* wk     = (const float*)d_in[3];
    const float* wv     = (const float*)d_in[4];
    const float* wo     = (const float*)d_in[5];
    const float* conv_q = (const float*)d_in[6];
    const float* conv_k = (const float*)d_in[7];
    const float* conv_v = (const float*)d_in[8];
    const float* gamma_q= (const float*)d_in[9];
    const float* gamma_k= (const float*)d_in[10];
    const float* lr_w   = (const float*)d_in[11];
    const float* lr_b   = (const float*)d_in[12];
    const float* decay_w= (const float*)d_in[13];
    const float* decay_b= (const float*)d_in[14];
    const float* mom_w  = (const float*)d_in[15];
    const float* mom_b  = (const float*)d_in[16];
    float* out = (float*)d_out;

    float *p_qp, *p_kp, *p_vp, *p_y;
    cudaGetSymbolAddress((void**)&p_qp, g_qp);
    cudaGetSymbolAddress((void**)&p_kp, g_kp);
    cudaGetSymbolAddress((void**)&p_vp, g_vp);
    cudaGetSymbolAddress((void**)&p_y,  g_y);

    int smG3 = 2*(2080 + 4*8*128) * (int)sizeof(unsigned);   // 49408
    int smG1 = 2*(2080 + 2*8*128) * (int)sizeof(unsigned);   // 33024
    int smA  = 17092 * (int)sizeof(float);
    int smB2 = 16900 * (int)sizeof(float);                   // 67600
    cudaFuncSetAttribute(k_gemm3, cudaFuncAttributeMaxDynamicSharedMemorySize, smG3);
    cudaFuncSetAttribute(k_gemm1, cudaFuncAttributeMaxDynamicSharedMemorySize, smG1);
    cudaFuncSetAttribute(k_chunkA, cudaFuncAttributeMaxDynamicSharedMemorySize, smA);
    cudaFuncSetAttribute(k_chunkB, cudaFuncAttributeMaxDynamicSharedMemorySize, smB2);

    k_rmsnorm<<<BN, 256>>>(x, w_rms);
    dim3 gqkv(DIi/256, BN/128, 4);   // z<3: QKV GEMM, z==3: gates
    k_gemm3<<<gqkv, 256, smG3>>>(wq, wk, wv, conv_q, conv_k, conv_v,
                                 lr_w, decay_w, mom_w, p_qp, p_kp, p_vp);
    k_chunkA<<<256, 256, smA>>>(lr_b, decay_b, mom_b, gamma_q, gamma_k);
    k_chunkB<<<64, 256, smB2>>>();
    dim3 gout(DIMM/128, BN/128);
    k_gemm1<<<gout, 256, smG1>>>(p_y, wo, out, DIMM, DIi);
}

// round 14
// speedup vs baseline: 1.1170x; 1.1170x over previous
#include <cuda_runtime.h>
#include <math.h>

#define Bb   2
#define Nn   1024
#define DIMM 1024
#define Hh   8
#define DHh  64
#define DIi  512
#define BN   (Bb*Nn)
#define NC   16          // chunks per (b,h)
#define CS   64          // chunk size

static __device__ __constant__ float EPSf = 1.1920929e-07f;

// ---------------- scratch ----------------
__device__ float g_xa[BN*DIMM];
__device__ float g_qp[BN*DIi];
__device__ float g_kp[BN*DIi];
__device__ float g_vp[BN*DIi];
__device__ float g_y [BN*DIi];
__device__ float g_ga[BN*24];
__device__ float g_gz[256*4096];
__device__ float g_gs[256*4096];
__device__ float g_si[256*4096];   // per-chunk input state S_in
__device__ float g_zi[256*4096];   // per-chunk input state Z_in
__device__ float g_sc[256*128];
__device__ float g_sc2[256*4];

// ---------------- tf32 helpers ----------------
__device__ __forceinline__ unsigned f2tf(float f) {
    unsigned r; asm("cvt.rna.tf32.f32 %0, %1;" : "=r"(r) : "f"(f)); return r;
}
__device__ __forceinline__ uint4 tf4(float4 v) {
    return make_uint4(f2tf(v.x), f2tf(v.y), f2tf(v.z), f2tf(v.w));
}
__device__ __forceinline__ void mma_tf32(float* c, const unsigned* a, const unsigned* b) {
    asm volatile(
        "mma.sync.aligned.m16n8k8.row.col.f32.tf32.tf32.f32 "
        "{%0,%1,%2,%3}, {%4,%5,%6,%7}, {%8,%9}, {%0,%1,%2,%3};"
        : "+f"(c[0]), "+f"(c[1]), "+f"(c[2]), "+f"(c[3])
        : "r"(a[0]), "r"(a[1]), "r"(a[2]), "r"(a[3]), "r"(b[0]), "r"(b[1]));
}

// ---------------- 1. RMSNorm ----------------
__global__ void k_rmsnorm(const float* __restrict__ x, const float* __restrict__ w) {
    int row = blockIdx.x;
    int tid = threadIdx.x;
    const float4* xr = (const float4*)(x + (size_t)row * DIMM);
    float4 xv = xr[tid];
    float ss = xv.x*xv.x + xv.y*xv.y + xv.z*xv.z + xv.w*xv.w;
    #pragma unroll
    for (int o = 16; o > 0; o >>= 1) ss += __shfl_xor_sync(0xffffffffu, ss, o);
    __shared__ float sred[8];
    if ((tid & 31) == 0) sred[tid >> 5] = ss;
    __syncthreads();
    float tot = 0.f;
    #pragma unroll
    for (int i = 0; i < 8; i++) tot += sred[i];
    float inv = rsqrtf(tot * (1.0f / DIMM) + EPSf);
    float4 wv = ((const float4*)w)[tid];
    float4 o;
    o.x = xv.x * inv * wv.x; o.y = xv.y * inv * wv.y;
    o.z = xv.z * inv * wv.z; o.w = xv.w * inv * wv.w;
    ((float4*)g_xa)[(size_t)row * (DIMM/4) + tid] = o;
}

// ---------------- gates body (runs inside k_gemm3's shadow) ----------------
__device__ void gates_body(const float* __restrict__ lw, const float* __restrict__ dw,
                           const float* __restrict__ mw, int gb, void* smraw) {
    float* As = (float*)smraw;            // [64][20]
    float* Ws = (float*)smraw + 64*20;    // [16][24]
    int tid = threadIdx.x;
    int hh = tid & 7, ty = tid >> 3;
    int row0 = gb * 64;
    float acc[2][3] = {};
    for (int k0 = 0; k0 < DIMM; k0 += 16) {
        {
            int mm = tid >> 2, kq = (tid & 3) * 4;
            float4 v = *(const float4*)(g_xa + (size_t)(row0+mm)*DIMM + k0 + kq);
            As[mm*20+kq+0]=v.x; As[mm*20+kq+1]=v.y; As[mm*20+kq+2]=v.z; As[mm*20+kq+3]=v.w;
        }
        if (tid < 128) {
            int kk = tid >> 3, h2 = tid & 7;
            Ws[kk*24+h2]    = lw[(k0+kk)*Hh + h2];
            Ws[kk*24+8+h2]  = dw[(k0+kk)*Hh + h2];
            Ws[kk*24+16+h2] = mw[(k0+kk)*Hh + h2];
        }
        __syncthreads();
        #pragma unroll
        for (int kk = 0; kk < 16; kk++) {
            float a0 = As[(ty*2)*20+kk], a1 = As[(ty*2+1)*20+kk];
            float w0 = Ws[kk*24+hh], w1 = Ws[kk*24+8+hh], w2 = Ws[kk*24+16+hh];
            acc[0][0] += a0*w0; acc[0][1] += a0*w1; acc[0][2] += a0*w2;
            acc[1][0] += a1*w0; acc[1][1] += a1*w1; acc[1][2] += a1*w2;
        }
        __syncthreads();
    }
    #pragma unroll
    for (int i = 0; i < 2; i++) {
        int row = row0 + ty*2 + i;
        g_ga[row*24 + hh]      = acc[i][0];
        g_ga[row*24 + 8 + hh]  = acc[i][1];
        g_ga[row*24 + 16 + hh] = acc[i][2];
    }
}

// ---------------- 2. tf32 GEMM core: double-buffered smem -----------------
template<bool FC, int MI, int WCN>
__device__ __forceinline__ void gemm_tc(const float* __restrict__ A,
                                        const float* __restrict__ Bm,
                                        float* __restrict__ C,
                                        int Nc, int Kc,
                                        const float* __restrict__ cw) {
    extern __shared__ unsigned smem[];
    unsigned* As = smem;                  // [2][4*520]
    unsigned* Bs = smem + 2*2080;         // [2][WCN*8*128]
    const int BSW = WCN*8*128;
    int tid = threadIdx.x;
    int lane = tid & 31, wid = tid >> 5;
    int wr = wid / WCN, wc = wid % WCN;
    int gid = lane >> 2, tig = lane & 3;
    int row0 = blockIdx.y * 128, col0 = blockIdx.x * (WCN*64);

    int ar = tid >> 1;
    int kqb = (tid & 1) * 2;
    int bk = lane >> 1, bq = lane & 1;

    int m = row0 + ar;
    int tloc = 0, b0 = 0;
    if (FC) { b0 = m & ~(Nn - 1); tloc = m - b0; }

    float acc[MI][8][4];
    #pragma unroll
    for (int i = 0; i < MI; i++)
        #pragma unroll
        for (int j = 0; j < 8; j++)
            #pragma unroll
            for (int q = 0; q < 4; q++) acc[i][j][q] = 0.f;

    float4 ra[2], rb[WCN];
    const float4* A4 = (const float4*)A;
    const float4* B4 = (const float4*)Bm;
    const float4* XA4 = (const float4*)g_xa;
    const float4* CW4 = (const float4*)cw;

    #define PREFETCH(kn)                                                        \
    {                                                                           \
        _Pragma("unroll")                                                       \
        for (int p = 0; p < 2; p++) {                                           \
            int kq = kqb + p;                                                   \
            if (!FC) {                                                          \
                ra[p] = A4[(size_t)m * (Kc >> 2) + ((kn) >> 2) + kq];           \
            } else {                                                            \
                int kb = (kn) + kq * 4;                                         \
                float we[4][4];                                                 \
                _Pragma("unroll")                                               \
                for (int e = 0; e < 4; e++) *(float4*)we[e] = CW4[kb + e];      \
                float4 r = make_float4(0.f, 0.f, 0.f, 0.f);                     \
                _Pragma("unroll")                                               \
                for (int j = 0; j < 4; j++) {                                   \
                    int tl = tloc + j - 2;                                      \
                    if ((unsigned)tl < (unsigned)Nn) {                          \
                        float4 xv = XA4[(size_t)(b0 + tl) * (DIMM >> 2) + (kb >> 2)]; \
                        r.x += xv.x * we[0][j]; r.y += xv.y * we[1][j];         \
                        r.z += xv.z * we[2][j]; r.w += xv.w * we[3][j];         \
                    }                                                           \
                }                                                               \
                ra[p] = r;                                                      \
            }                                                                   \
        }                                                                       \
        _Pragma("unroll")                                                       \
        for (int p = 0; p < WCN; p++) {                                         \
            int nt = wid + p * 8;                                               \
            rb[p] = B4[(size_t)((kn) + bk) * (Nc >> 2) + (col0 >> 2) + nt * 2 + bq]; \
        }                                                                       \
    }

    #define STORE(buf)                                                          \
    {                                                                           \
        unsigned* Aw = As + (buf)*2080;                                         \
        unsigned* Bw = Bs + (buf)*BSW;                                          \
        _Pragma("unroll")                                                       \
        for (int p = 0; p < 2; p++)                                             \
            *(uint4*)&Aw[(kqb+p)*520 + ar*4] = tf4(ra[p]);                      \
        _Pragma("unroll")                                                       \
        for (int p = 0; p < WCN; p++) {                                         \
            int nt = wid + p * 8;                                               \
            *(uint4*)&Bw[nt*128 + bk*8 + bq*4] = tf4(rb[p]);                    \
        }                                                                       \
    }

    PREFETCH(0)
    STORE(0)
    __syncthreads();

    for (int k0 = 0; k0 < Kc; k0 += 16) {
        int cur = (k0 >> 4) & 1;
        bool more = (k0 + 16 < Kc);
        if (more) PREFETCH(k0 + 16)
        const unsigned* Abuf = As + cur*2080;
        const unsigned* Bbuf = Bs + cur*BSW;
        #pragma unroll
        for (int c = 0; c < 2; c++) {
            unsigned a[MI][4];
            const unsigned* s0 = Abuf + (c*2)*520;
            const unsigned* s1 = Abuf + (c*2+1)*520;
            #pragma unroll
            for (int mi = 0; mi < MI; mi++) {
                int m0 = (wr*MI + mi) * 16;
                a[mi][0] = s0[(m0+gid)*4 + tig];
                a[mi][1] = s0[(m0+gid+8)*4 + tig];
                a[mi][2] = s1[(m0+gid)*4 + tig];
                a[mi][3] = s1[(m0+gid+8)*4 + tig];
            }
            #pragma unroll
            for (int ni = 0; ni < 8; ni++) {
                int nt = wc*8 + ni;
                unsigned b[2];
                b[0] = Bbuf[nt*128 + (c*8+tig)*8 + gid];
                b[1] = Bbuf[nt*128 + (c*8+tig+4)*8 + gid];
                #pragma unroll
                for (int mi = 0; mi < MI; mi++) mma_tf32(acc[mi][ni], a[mi], b);
            }
        }
        if (more) {
            STORE(cur ^ 1)
            __syncthreads();
        }
    }
    #undef PREFETCH
    #undef STORE

    #pragma unroll
    for (int mi = 0; mi < MI; mi++) {
        #pragma unroll
        for (int ni = 0; ni < 8; ni++) {
            int row = row0 + (wr*MI + mi)*16 + gid;
            int col = col0 + (wc*8 + ni)*8 + tig*2;
            *(float2*)(C + (size_t)row * Nc + col) =
                make_float2(acc[mi][ni][0], acc[mi][ni][1]);
            *(float2*)(C + (size_t)(row+8) * Nc + col) =
                make_float2(acc[mi][ni][2], acc[mi][ni][3]);
        }
    }
}

// z<3: QKV GEMM tiles; z==3: gate projections (fills idle SMs of the wave)
__global__ __launch_bounds__(256, 1)
void k_gemm3(const float* __restrict__ B0, const float* __restrict__ B1,
             const float* __restrict__ B2,
             const float* __restrict__ cw0, const float* __restrict__ cw1,
             const float* __restrict__ cw2,
             const float* __restrict__ lw, const float* __restrict__ dw,
             const float* __restrict__ mw,
             float* __restrict__ C0, float* __restrict__ C1,
             float* __restrict__ C2) {
    if (blockIdx.z < 3) {
        const float* Bm = (blockIdx.z == 0) ? B0 : ((blockIdx.z == 1) ? B1 : B2);
        const float* cw = (blockIdx.z == 0) ? cw0 : ((blockIdx.z == 1) ? cw1 : cw2);
        float* C = (blockIdx.z == 0) ? C0 : ((blockIdx.z == 1) ? C1 : C2);
        gemm_tc<true, 4, 4>(nullptr, Bm, C, DIi, DIMM, cw);
    } else {
        extern __shared__ unsigned smraw[];
        int gb = blockIdx.y * 2 + blockIdx.x;   // 0..31
        gates_body(lw, dw, mw, gb, (void*)smraw);
    }
}

__global__ __launch_bounds__(256, 1)
void k_gemm1(const float* __restrict__ A, const float* __restrict__ Bm,
             float* __restrict__ C, int Nc, int Kc) {
    gemm_tc<false, 2, 2>(A, Bm, C, Nc, Kc, nullptr);
}

// ---------------- 4a. chunk kernel A (+ fused per-head RMSNorm) -----------
__global__ __launch_bounds__(256, 1)
void k_chunkA(const float* __restrict__ lb, const float* __restrict__ db,
              const float* __restrict__ mb,
              const float* __restrict__ gq, const float* __restrict__ gk) {
    extern __shared__ float sm[];
    float* sq  = sm;            // 64x65, reused as T
    float* sk  = sm + 4160;
    float* sv  = sm + 8320;
    float* sE  = sm + 12480;
    float* slr = sm + 16640;
    float* sde = sm + 16704;
    float* smo = sm + 16768;
    float* sAe = sm + 16832;
    float* sEe = sm + 16896;
    float* ssc = sm + 16960;
    float* ssc2= sm + 17088;

    int tid = threadIdx.x;
    int cc = blockIdx.x;
    int bh = cc >> 4, c = cc & 15;
    int b = bh >> 3, h = bh & 7;
    int t0 = c * CS;
    const size_t base = (size_t)b * Nn * DIi + h * DHh;

    {
        int f4 = tid & 15, r0 = tid >> 4;
        #pragma unroll
        for (int rr = 0; rr < 4; rr++) {
            int row = rr*16 + r0;
            size_t g = base + (size_t)(t0+row)*DIi + f4*4;
            float4 vq = *(const float4*)(g_qp + g);
            float4 vk = *(const float4*)(g_kp + g);
            float4 vv = *(const float4*)(g_vp + g);
            int so = row*65 + f4*4;
            sq[so]=vq.x; sq[so+1]=vq.y; sq[so+2]=vq.z; sq[so+3]=vq.w;
            sk[so]=vk.x; sk[so+1]=vk.y; sk[so+2]=vk.z; sk[so+3]=vk.w;
            sv[so]=vv.x; sv[so+1]=vv.y; sv[so+2]=vv.z; sv[so+3]=vv.w;
        }
    }
    if (tid < 192) {
        int i = tid / 3, gi = tid - i*3;
        const float* bb = (gi==0) ? lb : ((gi==1) ? db : mb);
        float raw = g_ga[(size_t)(b*Nn + t0 + i)*24 + gi*8 + h] + bb[h];
        float v = 1.f/(1.f+__expf(-raw));
        ((gi==0) ? slr : ((gi==1) ? sde : smo))[i] = v;
    }
    __syncthreads();

    {
        int row = tid >> 2, seg = (tid & 3) * 16;
        float ssq = 0.f, ssk = 0.f;
        #pragma unroll
        for (int j = 0; j < 16; j++) {
            float a = sq[row*65 + seg + j]; ssq += a*a;
            float e = sk[row*65 + seg + j]; ssk += e*e;
        }
        ssq += __shfl_xor_sync(0xffffffffu, ssq, 1);
        ssq += __shfl_xor_sync(0xffffffffu, ssq, 2);
        ssk += __shfl_xor_sync(0xffffffffu, ssk, 1);
        ssk += __shfl_xor_sync(0xffffffffu, ssk, 2);
        float invq = 1.f / fmaxf(sqrtf(ssq) * 0.125f, 1e-8f);
        float invk = 1.f / fmaxf(sqrtf(ssk) * 0.125f, 1e-8f);
        float qb[16];
        #pragma unroll
        for (int j = 0; j < 16; j++) {
            float nq = sq[row*65 + seg + j] * invq * gq[h*DHh + seg + j];
            sq[row*65 + seg + j] = nq; qb[j] = nq;
            sk[row*65 + seg + j] = sk[row*65 + seg + j] * invk * gk[h*DHh + seg + j];
        }
        #pragma unroll
        for (int j = 0; j < 4; j++)
            *(float4*)(g_qp + base + (size_t)(t0+row)*DIi + seg + j*4) =
                make_float4(qb[j*4], qb[j*4+1], qb[j*4+2], qb[j*4+3]);
    }
    if (tid < 64) {
        int u = tid;
        float A_=0.f, E_=0.f, Amul=1.f, Dmul=1.f, F=0.f;
        for (int i = 0; i < 64; i++) {
            sE[i*65 + u] = E_;
            if (u == i) { ssc[i*2] = Dmul; ssc[i*2+1] = F; }
            float ai = smo[i], di = sde[i], li = slr[i];
            A_ = ai * A_; if (u == i) A_ = 1.f;
            E_ = di * E_ + li * A_;
            Amul *= ai; F = di * F + li * Amul; Dmul *= di;
        }
        sAe[u] = A_; sEe[u] = E_;
        if (u == 0) { ssc2[0] = Amul; ssc2[1] = Dmul; ssc2[2] = F; }
    }
    __syncthreads();

    int tx = tid & 15, ty = tid >> 4;
    float a1[4][4];
    #pragma unroll
    for (int i = 0; i < 4; i++)
        #pragma unroll
        for (int j = 0; j < 4; j++) a1[i][j] = 0.f;
    for (int p = 0; p < 64; p++) {
        float aa[4], bb[4];
        #pragma unroll
        for (int j = 0; j < 4; j++) aa[j] = sq[(ty*4+j)*65 + p];
        #pragma unroll
        for (int j = 0; j < 4; j++) bb[j] = sk[(tx*4+j)*65 + p];
        #pragma unroll
        for (int i = 0; i < 4; i++)
            #pragma unroll
            for (int j = 0; j < 4; j++) a1[i][j] += aa[i]*bb[j];
    }
    __syncthreads();
    #pragma unroll
    for (int i = 0; i < 4; i++)
        #pragma unroll
        for (int j = 0; j < 4; j++)
            sq[(ty*4+i)*65 + tx*4+j] = a1[i][j] * sE[(ty*4+i)*65 + tx*4+j];
    __syncthreads();

    float a2[4][4];
    #pragma unroll
    for (int i = 0; i < 4; i++)
        #pragma unroll
        for (int j = 0; j < 4; j++) a2[i][j] = 0.f;
    for (int u = 0; u < 64; u++) {
        float aa[4], bb[4];
        #pragma unroll
        for (int j = 0; j < 4; j++) aa[j] = sq[(ty*4+j)*65 + u];
        #pragma unroll
        for (int j = 0; j < 4; j++) bb[j] = sv[u*65 + tx*4+j];
        #pragma unroll
        for (int i = 0; i < 4; i++)
            #pragma unroll
            for (int j = 0; j < 4; j++) a2[i][j] += aa[i]*bb[j];
    }
    #pragma unroll
    for (int i = 0; i < 4; i++)
        *(float4*)(g_y + base + (size_t)(t0 + ty*4+i)*DIi + tx*4) =
            make_float4(a2[i][0], a2[i][1], a2[i][2], a2[i][3]);

    float az[4][4], as_[4][4];
    #pragma unroll
    for (int i = 0; i < 4; i++)
        #pragma unroll
        for (int j = 0; j < 4; j++) { az[i][j]=0.f; as_[i][j]=0.f; }
    for (int u = 0; u < 64; u++) {
        float wz = sAe[u], ws = sEe[u];
        float aa[4], bb[4];
        #pragma unroll
        for (int j = 0; j < 4; j++) aa[j] = sv[u*65 + ty*4+j];
        #pragma unroll
        for (int j = 0; j < 4; j++) bb[j] = sk[u*65 + tx*4+j];
        #pragma unroll
        for (int i = 0; i < 4; i++) {
            float azw = wz*aa[i], asw = ws*aa[i];
            #pragma unroll
            for (int j = 0; j < 4; j++) { az[i][j] += azw*bb[j]; as_[i][j] += asw*bb[j]; }
        }
    }
    #pragma unroll
    for (int i = 0; i < 4; i++) {
        size_t go = (size_t)cc*4096 + (ty*4+i)*64 + tx*4;
        *(float4*)(g_gz + go) = make_float4(az[i][0], az[i][1], az[i][2], az[i][3]);
        *(float4*)(g_gs + go) = make_float4(as_[i][0], as_[i][1], as_[i][2], as_[i][3]);
    }
    if (tid < 128) g_sc[(size_t)cc*128 + tid] = ssc[tid];
    if (tid >= 128 && tid < 131) g_sc2[(size_t)cc*4 + (tid-128)] = ssc2[tid-128];
}

// ---------------- 4b. carry recurrence: register-resident, no barriers ----
// 64 blocks = 16 bh x 4 quarter-tiles (1024 elems each). Each thread owns
// 4 consecutive elements of S and Z. Writes each chunk's INPUT state.
__global__ __launch_bounds__(256, 1)
void k_carry() {
    int bh = blockIdx.x >> 2, sl = blockIdx.x & 3;
    int idx = sl*1024 + threadIdx.x*4;
    float4 S = make_float4(0.f,0.f,0.f,0.f), Z = make_float4(0.f,0.f,0.f,0.f);
    size_t cc0 = (size_t)bh * 16;
    float4 gz = *(const float4*)(g_gz + cc0*4096 + idx);
    float4 gs = *(const float4*)(g_gs + cc0*4096 + idx);
    float a_ = g_sc2[cc0*4+0], d_ = g_sc2[cc0*4+1], f_ = g_sc2[cc0*4+2];
    for (int c = 0; c < NC; c++) {
        size_t cc = cc0 + c;
        *(float4*)(g_si + cc*4096 + idx) = S;
        *(float4*)(g_zi + cc*4096 + idx) = Z;
        float4 ngz = make_float4(0.f,0.f,0.f,0.f);
        float4 ngs = make_float4(0.f,0.f,0.f,0.f);
        float na = 0.f, nd = 0.f, nf = 0.f;
        if (c + 1 < NC) {
            ngz = *(const float4*)(g_gz + (cc+1)*4096 + idx);
            ngs = *(const float4*)(g_gs + (cc+1)*4096 + idx);
            na = g_sc2[(cc+1)*4+0]; nd = g_sc2[(cc+1)*4+1]; nf = g_sc2[(cc+1)*4+2];
        }
        float4 Sn;
        Sn.x = d_*S.x - f_*Z.x + gs.x;  Z.x = a_*Z.x - gz.x;
        Sn.y = d_*S.y - f_*Z.y + gs.y;  Z.y = a_*Z.y - gz.y;
        Sn.z = d_*S.z - f_*Z.z + gs.z;  Z.z = a_*Z.z - gz.z;
        Sn.w = d_*S.w - f_*Z.w + gs.w;  Z.w = a_*Z.w - gz.w;
        S = Sn;
        gz = ngz; gs = ngs; a_ = na; d_ = nd; f_ = nf;
    }
}

// ---------------- 4c. cross terms: fully parallel over 256 chunks ---------
// y[t] += Dm(i-1) * (Q S_in^T) - F(i-1) * (Q Z_in^T)
__global__ __launch_bounds__(256, 1)
void k_cross() {
    extern __shared__ float smC[];
    float* sQ  = smC;           // 64x65
    float* sS  = smC + 4160;    // 64x65
    float* sZ  = smC + 8320;    // 64x65
    float* ssc = smC + 12480;   // 128
    int cc = blockIdx.x;
    int bh = cc >> 4, c = cc & 15;
    if (c == 0) return;         // S_in = Z_in = 0, no contribution
    int b = bh >> 3, h = bh & 7;
    int t0 = c * CS;
    const size_t base = (size_t)b * Nn * DIi + h * DHh;
    int tid = threadIdx.x;
    int lane = tid & 31, wid = tid >> 5;
    int g = lane >> 2, t4 = lane & 3;
    int wm = wid & 3, wn = wid >> 2;
    int i0 = wm * 16;
    int f4 = tid & 15, r0q = tid >> 4;

    #pragma unroll
    for (int rr = 0; rr < 4; rr++) {
        int row = rr*16 + r0q;
        float4 q = *(const float4*)(g_qp + base + (size_t)(t0+row)*DIi + f4*4);
        float4 s = *(const float4*)(g_si + (size_t)cc*4096 + row*64 + f4*4);
        float4 z = *(const float4*)(g_zi + (size_t)cc*4096 + row*64 + f4*4);
        int so = row*65 + f4*4;
        sQ[so]=q.x; sQ[so+1]=q.y; sQ[so+2]=q.z; sQ[so+3]=q.w;
        sS[so]=s.x; sS[so+1]=s.y; sS[so+2]=s.z; sS[so+3]=s.w;
        sZ[so]=z.x; sZ[so+1]=z.y; sZ[so+2]=z.z; sZ[so+3]=z.w;
    }
    if (tid < 128) ssc[tid] = g_sc[(size_t)cc*128 + tid];
    __syncthreads();

    float y1[4][4], y2[4][4];
    #pragma unroll
    for (int ni = 0; ni < 4; ni++)
        #pragma unroll
        for (int q = 0; q < 4; q++) { y1[ni][q] = 0.f; y2[ni][q] = 0.f; }

    #pragma unroll
    for (int k0 = 0; k0 < 64; k0 += 8) {
        unsigned a[4];
        a[0] = f2tf(sQ[(i0+g)*65   + k0+t4]);
        a[1] = f2tf(sQ[(i0+g+8)*65 + k0+t4]);
        a[2] = f2tf(sQ[(i0+g)*65   + k0+t4+4]);
        a[3] = f2tf(sQ[(i0+g+8)*65 + k0+t4+4]);
        #pragma unroll
        for (int ni = 0; ni < 4; ni++) {
            int r0 = wn*32 + ni*8;
            unsigned bs[2], bz[2];
            bs[0] = f2tf(sS[(r0+g)*65 + k0+t4]);
            bs[1] = f2tf(sS[(r0+g)*65 + k0+t4+4]);
            bz[0] = f2tf(sZ[(r0+g)*65 + k0+t4]);
            bz[1] = f2tf(sZ[(r0+g)*65 + k0+t4+4]);
            mma_tf32(y1[ni], a, bs);
            mma_tf32(y2[ni], a, bz);
        }
    }
    float dm0 = ssc[(i0+g)*2],     f0 = ssc[(i0+g)*2+1];
    float dm1 = ssc[(i0+g+8)*2],   f1 = ssc[(i0+g+8)*2+1];
    #pragma unroll
    for (int ni = 0; ni < 4; ni++) {
        int r0 = wn*32 + ni*8 + 2*t4;
        float* p0 = g_y + base + (size_t)(t0+i0+g)*DIi + r0;
        float* p1 = g_y + base + (size_t)(t0+i0+g+8)*DIi + r0;
        float2 e0 = *(float2*)p0, e1 = *(float2*)p1;
        e0.x += dm0*y1[ni][0] - f0*y2[ni][0];
        e0.y += dm0*y1[ni][1] - f0*y2[ni][1];
        e1.x += dm1*y1[ni][2] - f1*y2[ni][2];
        e1.y += dm1*y1[ni][3] - f1*y2[ni][3];
        *(float2*)p0 = e0; *(float2*)p1 = e1;
    }
}

// ---------------- launch ----------------
extern "C" void kernel_launch(void* const* d_in, const int* in_sizes, int n_in,
                              void* d_out, int out_size) {
    const float* x      = (const float*)d_in[0];
    const float* w_rms  = (const float*)d_in[1];
    const float* wq     = (const float*)d_in[2];
    const float* wk     = (const float*)d_in[3];
    const float* wv     = (const float*)d_in[4];
    const float* wo     = (const float*)d_in[5];
    const float* conv_q = (const float*)d_in[6];
    const float* conv_k = (const float*)d_in[7];
    const float* conv_v = (const float*)d_in[8];
    const float* gamma_q= (const float*)d_in[9];
    const float* gamma_k= (const float*)d_in[10];
    const float* lr_w   = (const float*)d_in[11];
    const float* lr_b   = (const float*)d_in[12];
    const float* decay_w= (const float*)d_in[13];
    const float* decay_b= (const float*)d_in[14];
    const float* mom_w  = (const float*)d_in[15];
    const float* mom_b  = (const float*)d_in[16];
    float* out = (float*)d_out;

    float *p_qp, *p_kp, *p_vp, *p_y;
    cudaGetSymbolAddress((void**)&p_qp, g_qp);
    cudaGetSymbolAddress((void**)&p_kp, g_kp);
    cudaGetSymbolAddress((void**)&p_vp, g_vp);
    cudaGetSymbolAddress((void**)&p_y,  g_y);

    int smG3 = 2*(2080 + 4*8*128) * (int)sizeof(unsigned);   // 49408
    int smG1 = 2*(2080 + 2*8*128) * (int)sizeof(unsigned);   // 33024
    int smA  = 17092 * (int)sizeof(float);
    int smC  = 12608 * (int)sizeof(float);                   // 50432
    cudaFuncSetAttribute(k_gemm3, cudaFuncAttributeMaxDynamicSharedMemorySize, smG3);
    cudaFuncSetAttribute(k_gemm1, cudaFuncAttributeMaxDynamicSharedMemorySize, smG1);
    cudaFuncSetAttribute(k_chunkA, cudaFuncAttributeMaxDynamicSharedMemorySize, smA);
    cudaFuncSetAttribute(k_cross, cudaFuncAttributeMaxDynamicSharedMemorySize, smC);

    k_rmsnorm<<<BN, 256>>>(x, w_rms);
    dim3 gqkv(DIi/256, BN/128, 4);   // z<3: QKV GEMM, z==3: gates
    k_gemm3<<<gqkv, 256, smG3>>>(wq, wk, wv, conv_q, conv_k, conv_v,
                                 lr_w, decay_w, mom_w, p_qp, p_kp, p_vp);
    k_chunkA<<<256, 256, smA>>>(lr_b, decay_b, mom_b, gamma_q, gamma_k);
    k_carry<<<64, 256>>>();
    k_cross<<<256, 256, smC>>>();
    dim3 gout(DIMM/128, BN/128);
    k_gemm1<<<gout, 256, smG1>>>(p_y, wo, out, DIMM, DIi);
}

// round 15
// speedup vs baseline: 1.1203x; 1.0030x over previous
#include <cuda_runtime.h>
#include <math.h>

#define Bb   2
#define Nn   1024
#define DIMM 1024
#define Hh   8
#define DHh  64
#define DIi  512
#define BN   (Bb*Nn)
#define NC   16          // chunks per (b,h)
#define CS   64          // chunk size

static __device__ __constant__ float EPSf = 1.1920929e-07f;

// ---------------- scratch ----------------
__device__ float g_xa[BN*DIMM];
__device__ float g_qp[BN*DIi];
__device__ float g_kp[BN*DIi];
__device__ float g_vp[BN*DIi];
__device__ float g_y [BN*DIi];
__device__ float g_ga[BN*24];
__device__ float g_gz[256*4096];
__device__ float g_gs[256*4096];
__device__ float g_si[256*4096];   // per-chunk input state S_in
__device__ float g_zi[256*4096];   // per-chunk input state Z_in
__device__ float g_sc[256*128];
__device__ float g_sc2[256*4];

// ---------------- tf32 helpers ----------------
__device__ __forceinline__ unsigned f2tf(float f) {
    unsigned r; asm("cvt.rna.tf32.f32 %0, %1;" : "=r"(r) : "f"(f)); return r;
}
__device__ __forceinline__ uint4 tf4(float4 v) {
    return make_uint4(f2tf(v.x), f2tf(v.y), f2tf(v.z), f2tf(v.w));
}
__device__ __forceinline__ void mma_tf32(float* c, const unsigned* a, const unsigned* b) {
    asm volatile(
        "mma.sync.aligned.m16n8k8.row.col.f32.tf32.tf32.f32 "
        "{%0,%1,%2,%3}, {%4,%5,%6,%7}, {%8,%9}, {%0,%1,%2,%3};"
        : "+f"(c[0]), "+f"(c[1]), "+f"(c[2]), "+f"(c[3])
        : "r"(a[0]), "r"(a[1]), "r"(a[2]), "r"(a[3]), "r"(b[0]), "r"(b[1]));
}

// ---------------- 1. RMSNorm ----------------
__global__ void k_rmsnorm(const float* __restrict__ x, const float* __restrict__ w) {
    int row = blockIdx.x;
    int tid = threadIdx.x;
    const float4* xr = (const float4*)(x + (size_t)row * DIMM);
    float4 xv = xr[tid];
    float ss = xv.x*xv.x + xv.y*xv.y + xv.z*xv.z + xv.w*xv.w;
    #pragma unroll
    for (int o = 16; o > 0; o >>= 1) ss += __shfl_xor_sync(0xffffffffu, ss, o);
    __shared__ float sred[8];
    if ((tid & 31) == 0) sred[tid >> 5] = ss;
    __syncthreads();
    float tot = 0.f;
    #pragma unroll
    for (int i = 0; i < 8; i++) tot += sred[i];
    float inv = rsqrtf(tot * (1.0f / DIMM) + EPSf);
    float4 wv = ((const float4*)w)[tid];
    float4 o;
    o.x = xv.x * inv * wv.x; o.y = xv.y * inv * wv.y;
    o.z = xv.z * inv * wv.z; o.w = xv.w * inv * wv.w;
    ((float4*)g_xa)[(size_t)row * (DIMM/4) + tid] = o;
}

// ---------------- gates body (runs inside k_gemm3's shadow) ----------------
__device__ void gates_body(const float* __restrict__ lw, const float* __restrict__ dw,
                           const float* __restrict__ mw, int gb, void* smraw) {
    float* As = (float*)smraw;            // [64][20]
    float* Ws = (float*)smraw + 64*20;    // [16][24]
    int tid = threadIdx.x;
    int hh = tid & 7, ty = tid >> 3;
    int row0 = gb * 64;
    float acc[2][3] = {};
    for (int k0 = 0; k0 < DIMM; k0 += 16) {
        {
            int mm = tid >> 2, kq = (tid & 3) * 4;
            float4 v = *(const float4*)(g_xa + (size_t)(row0+mm)*DIMM + k0 + kq);
            As[mm*20+kq+0]=v.x; As[mm*20+kq+1]=v.y; As[mm*20+kq+2]=v.z; As[mm*20+kq+3]=v.w;
        }
        if (tid < 128) {
            int kk = tid >> 3, h2 = tid & 7;
            Ws[kk*24+h2]    = lw[(k0+kk)*Hh + h2];
            Ws[kk*24+8+h2]  = dw[(k0+kk)*Hh + h2];
            Ws[kk*24+16+h2] = mw[(k0+kk)*Hh + h2];
        }
        __syncthreads();
        #pragma unroll
        for (int kk = 0; kk < 16; kk++) {
            float a0 = As[(ty*2)*20+kk], a1 = As[(ty*2+1)*20+kk];
            float w0 = Ws[kk*24+hh], w1 = Ws[kk*24+8+hh], w2 = Ws[kk*24+16+hh];
            acc[0][0] += a0*w0; acc[0][1] += a0*w1; acc[0][2] += a0*w2;
            acc[1][0] += a1*w0; acc[1][1] += a1*w1; acc[1][2] += a1*w2;
        }
        __syncthreads();
    }
    #pragma unroll
    for (int i = 0; i < 2; i++) {
        int row = row0 + ty*2 + i;
        g_ga[row*24 + hh]      = acc[i][0];
        g_ga[row*24 + 8 + hh]  = acc[i][1];
        g_ga[row*24 + 16 + hh] = acc[i][2];
    }
}

// ---------------- 2. tf32 GEMM core: double-buffered smem -----------------
template<bool FC, int MI, int WCN>
__device__ __forceinline__ void gemm_tc(const float* __restrict__ A,
                                        const float* __restrict__ Bm,
                                        float* __restrict__ C,
                                        int Nc, int Kc,
                                        const float* __restrict__ cw) {
    extern __shared__ unsigned smem[];
    unsigned* As = smem;                  // [2][4*520]
    unsigned* Bs = smem + 2*2080;         // [2][WCN*8*128]
    const int BSW = WCN*8*128;
    int tid = threadIdx.x;
    int lane = tid & 31, wid = tid >> 5;
    int wr = wid / WCN, wc = wid % WCN;
    int gid = lane >> 2, tig = lane & 3;
    int row0 = blockIdx.y * 128, col0 = blockIdx.x * (WCN*64);

    int ar = tid >> 1;
    int kqb = (tid & 1) * 2;
    int bk = lane >> 1, bq = lane & 1;

    int m = row0 + ar;
    int tloc = 0, b0 = 0;
    if (FC) { b0 = m & ~(Nn - 1); tloc = m - b0; }

    float acc[MI][8][4];
    #pragma unroll
    for (int i = 0; i < MI; i++)
        #pragma unroll
        for (int j = 0; j < 8; j++)
            #pragma unroll
            for (int q = 0; q < 4; q++) acc[i][j][q] = 0.f;

    float4 ra[2], rb[WCN];
    const float4* A4 = (const float4*)A;
    const float4* B4 = (const float4*)Bm;
    const float4* XA4 = (const float4*)g_xa;
    const float4* CW4 = (const float4*)cw;

    #define PREFETCH(kn)                                                        \
    {                                                                           \
        _Pragma("unroll")                                                       \
        for (int p = 0; p < 2; p++) {                                           \
            int kq = kqb + p;                                                   \
            if (!FC) {                                                          \
                ra[p] = A4[(size_t)m * (Kc >> 2) + ((kn) >> 2) + kq];           \
            } else {                                                            \
                int kb = (kn) + kq * 4;                                         \
                float we[4][4];                                                 \
                _Pragma("unroll")                                               \
                for (int e = 0; e < 4; e++) *(float4*)we[e] = CW4[kb + e];      \
                float4 r = make_float4(0.f, 0.f, 0.f, 0.f);                     \
                _Pragma("unroll")                                               \
                for (int j = 0; j < 4; j++) {                                   \
                    int tl = tloc + j - 2;                                      \
                    if ((unsigned)tl < (unsigned)Nn) {                          \
                        float4 xv = XA4[(size_t)(b0 + tl) * (DIMM >> 2) + (kb >> 2)]; \
                        r.x += xv.x * we[0][j]; r.y += xv.y * we[1][j];         \
                        r.z += xv.z * we[2][j]; r.w += xv.w * we[3][j];         \
                    }                                                           \
                }                                                               \
                ra[p] = r;                                                      \
            }                                                                   \
        }                                                                       \
        _Pragma("unroll")                                                       \
        for (int p = 0; p < WCN; p++) {                                         \
            int nt = wid + p * 8;                                               \
            rb[p] = B4[(size_t)((kn) + bk) * (Nc >> 2) + (col0 >> 2) + nt * 2 + bq]; \
        }                                                                       \
    }

    #define STORE(buf)                                                          \
    {                                                                           \
        unsigned* Aw = As + (buf)*2080;                                         \
        unsigned* Bw = Bs + (buf)*BSW;                                          \
        _Pragma("unroll")                                                       \
        for (int p = 0; p < 2; p++)                                             \
            *(uint4*)&Aw[(kqb+p)*520 + ar*4] = tf4(ra[p]);                      \
        _Pragma("unroll")                                                       \
        for (int p = 0; p < WCN; p++) {                                         \
            int nt = wid + p * 8;                                               \
            *(uint4*)&Bw[nt*128 + bk*8 + bq*4] = tf4(rb[p]);                    \
        }                                                                       \
    }

    PREFETCH(0)
    STORE(0)
    __syncthreads();

    for (int k0 = 0; k0 < Kc; k0 += 16) {
        int cur = (k0 >> 4) & 1;
        bool more = (k0 + 16 < Kc);
        if (more) PREFETCH(k0 + 16)
        const unsigned* Abuf = As + cur*2080;
        const unsigned* Bbuf = Bs + cur*BSW;
        #pragma unroll
        for (int c = 0; c < 2; c++) {
            unsigned a[MI][4];
            const unsigned* s0 = Abuf + (c*2)*520;
            const unsigned* s1 = Abuf + (c*2+1)*520;
            #pragma unroll
            for (int mi = 0; mi < MI; mi++) {
                int m0 = (wr*MI + mi) * 16;
                a[mi][0] = s0[(m0+gid)*4 + tig];
                a[mi][1] = s0[(m0+gid+8)*4 + tig];
                a[mi][2] = s1[(m0+gid)*4 + tig];
                a[mi][3] = s1[(m0+gid+8)*4 + tig];
            }
            #pragma unroll
            for (int ni = 0; ni < 8; ni++) {
                int nt = wc*8 + ni;
                unsigned b[2];
                b[0] = Bbuf[nt*128 + (c*8+tig)*8 + gid];
                b[1] = Bbuf[nt*128 + (c*8+tig+4)*8 + gid];
                #pragma unroll
                for (int mi = 0; mi < MI; mi++) mma_tf32(acc[mi][ni], a[mi], b);
            }
        }
        if (more) {
            STORE(cur ^ 1)
            __syncthreads();
        }
    }
    #undef PREFETCH
    #undef STORE

    #pragma unroll
    for (int mi = 0; mi < MI; mi++) {
        #pragma unroll
        for (int ni = 0; ni < 8; ni++) {
            int row = row0 + (wr*MI + mi)*16 + gid;
            int col = col0 + (wc*8 + ni)*8 + tig*2;
            *(float2*)(C + (size_t)row * Nc + col) =
                make_float2(acc[mi][ni][0], acc[mi][ni][1]);
            *(float2*)(C + (size_t)(row+8) * Nc + col) =
                make_float2(acc[mi][ni][2], acc[mi][ni][3]);
        }
    }
}

// z<3: QKV GEMM tiles; z==3: gate projections (fills idle SMs of the wave)
__global__ __launch_bounds__(256, 1)
void k_gemm3(const float* __restrict__ B0, const float* __restrict__ B1,
             const float* __restrict__ B2,
             const float* __restrict__ cw0, const float* __restrict__ cw1,
             const float* __restrict__ cw2,
             const float* __restrict__ lw, const float* __restrict__ dw,
             const float* __restrict__ mw,
             float* __restrict__ C0, float* __restrict__ C1,
             float* __restrict__ C2) {
    if (blockIdx.z < 3) {
        const float* Bm = (blockIdx.z == 0) ? B0 : ((blockIdx.z == 1) ? B1 : B2);
        const float* cw = (blockIdx.z == 0) ? cw0 : ((blockIdx.z == 1) ? cw1 : cw2);
        float* C = (blockIdx.z == 0) ? C0 : ((blockIdx.z == 1) ? C1 : C2);
        gemm_tc<true, 4, 4>(nullptr, Bm, C, DIi, DIMM, cw);
    } else {
        extern __shared__ unsigned smraw[];
        int gb = blockIdx.y * 2 + blockIdx.x;   // 0..31
        gates_body(lw, dw, mw, gb, (void*)smraw);
    }
}

__global__ __launch_bounds__(256, 1)
void k_gemm1(const float* __restrict__ A, const float* __restrict__ Bm,
             float* __restrict__ C, int Nc, int Kc) {
    gemm_tc<false, 2, 2>(A, Bm, C, Nc, Kc, nullptr);
}

// ---------------- 4a. chunk kernel A (+ fused per-head RMSNorm) -----------
__global__ __launch_bounds__(256, 2)
void k_chunkA(const float* __restrict__ lb, const float* __restrict__ db,
              const float* __restrict__ mb,
              const float* __restrict__ gq, const float* __restrict__ gk) {
    extern __shared__ float sm[];
    float* sq  = sm;            // 64x65, reused as T
    float* sk  = sm + 4160;
    float* sv  = sm + 8320;
    float* sE  = sm + 12480;
    float* slr = sm + 16640;
    float* sde = sm + 16704;
    float* smo = sm + 16768;
    float* sAe = sm + 16832;
    float* sEe = sm + 16896;
    float* ssc = sm + 16960;
    float* ssc2= sm + 17088;

    int tid = threadIdx.x;
    int cc = blockIdx.x;
    int bh = cc >> 4, c = cc & 15;
    int b = bh >> 3, h = bh & 7;
    int t0 = c * CS;
    const size_t base = (size_t)b * Nn * DIi + h * DHh;

    {
        int f4 = tid & 15, r0 = tid >> 4;
        #pragma unroll
        for (int rr = 0; rr < 4; rr++) {
            int row = rr*16 + r0;
            size_t g = base + (size_t)(t0+row)*DIi + f4*4;
            float4 vq = *(const float4*)(g_qp + g);
            float4 vk = *(const float4*)(g_kp + g);
            float4 vv = *(const float4*)(g_vp + g);
            int so = row*65 + f4*4;
            sq[so]=vq.x; sq[so+1]=vq.y; sq[so+2]=vq.z; sq[so+3]=vq.w;
            sk[so]=vk.x; sk[so+1]=vk.y; sk[so+2]=vk.z; sk[so+3]=vk.w;
            sv[so]=vv.x; sv[so+1]=vv.y; sv[so+2]=vv.z; sv[so+3]=vv.w;
        }
    }
    if (tid < 192) {
        int i = tid / 3, gi = tid - i*3;
        const float* bb = (gi==0) ? lb : ((gi==1) ? db : mb);
        float raw = g_ga[(size_t)(b*Nn + t0 + i)*24 + gi*8 + h] + bb[h];
        float v = 1.f/(1.f+__expf(-raw));
        ((gi==0) ? slr : ((gi==1) ? sde : smo))[i] = v;
    }
    __syncthreads();

    {
        int row = tid >> 2, seg = (tid & 3) * 16;
        float ssq = 0.f, ssk = 0.f;
        #pragma unroll
        for (int j = 0; j < 16; j++) {
            float a = sq[row*65 + seg + j]; ssq += a*a;
            float e = sk[row*65 + seg + j]; ssk += e*e;
        }
        ssq += __shfl_xor_sync(0xffffffffu, ssq, 1);
        ssq += __shfl_xor_sync(0xffffffffu, ssq, 2);
        ssk += __shfl_xor_sync(0xffffffffu, ssk, 1);
        ssk += __shfl_xor_sync(0xffffffffu, ssk, 2);
        float invq = 1.f / fmaxf(sqrtf(ssq) * 0.125f, 1e-8f);
        float invk = 1.f / fmaxf(sqrtf(ssk) * 0.125f, 1e-8f);
        float qb[16];
        #pragma unroll
        for (int j = 0; j < 16; j++) {
            float nq = sq[row*65 + seg + j] * invq * gq[h*DHh + seg + j];
            sq[row*65 + seg + j] = nq; qb[j] = nq;
            sk[row*65 + seg + j] = sk[row*65 + seg + j] * invk * gk[h*DHh + seg + j];
        }
        #pragma unroll
        for (int j = 0; j < 4; j++)
            *(float4*)(g_qp + base + (size_t)(t0+row)*DIi + seg + j*4) =
                make_float4(qb[j*4], qb[j*4+1], qb[j*4+2], qb[j*4+3]);
    }
    if (tid < 64) {
        int u = tid;
        float A_=0.f, E_=0.f, Amul=1.f, Dmul=1.f, F=0.f;
        for (int i = 0; i < 64; i++) {
            sE[i*65 + u] = E_;
            if (u == i) { ssc[i*2] = Dmul; ssc[i*2+1] = F; }
            float ai = smo[i], di = sde[i], li = slr[i];
            A_ = ai * A_; if (u == i) A_ = 1.f;
            E_ = di * E_ + li * A_;
            Amul *= ai; F = di * F + li * Amul; Dmul *= di;
        }
        sAe[u] = A_; sEe[u] = E_;
        if (u == 0) { ssc2[0] = Amul; ssc2[1] = Dmul; ssc2[2] = F; }
    }
    __syncthreads();

    int tx = tid & 15, ty = tid >> 4;
    float a1[4][4];
    #pragma unroll
    for (int i = 0; i < 4; i++)
        #pragma unroll
        for (int j = 0; j < 4; j++) a1[i][j] = 0.f;
    for (int p = 0; p < 64; p++) {
        float aa[4], bb[4];
        #pragma unroll
        for (int j = 0; j < 4; j++) aa[j] = sq[(ty*4+j)*65 + p];
        #pragma unroll
        for (int j = 0; j < 4; j++) bb[j] = sk[(tx*4+j)*65 + p];
        #pragma unroll
        for (int i = 0; i < 4; i++)
            #pragma unroll
            for (int j = 0; j < 4; j++) a1[i][j] += aa[i]*bb[j];
    }
    __syncthreads();
    #pragma unroll
    for (int i = 0; i < 4; i++)
        #pragma unroll
        for (int j = 0; j < 4; j++)
            sq[(ty*4+i)*65 + tx*4+j] = a1[i][j] * sE[(ty*4+i)*65 + tx*4+j];
    __syncthreads();

    float a2[4][4];
    #pragma unroll
    for (int i = 0; i < 4; i++)
        #pragma unroll
        for (int j = 0; j < 4; j++) a2[i][j] = 0.f;
    for (int u = 0; u < 64; u++) {
        float aa[4], bb[4];
        #pragma unroll
        for (int j = 0; j < 4; j++) aa[j] = sq[(ty*4+j)*65 + u];
        #pragma unroll
        for (int j = 0; j < 4; j++) bb[j] = sv[u*65 + tx*4+j];
        #pragma unroll
        for (int i = 0; i < 4; i++)
            #pragma unroll
            for (int j = 0; j < 4; j++) a2[i][j] += aa[i]*bb[j];
    }
    #pragma unroll
    for (int i = 0; i < 4; i++)
        *(float4*)(g_y + base + (size_t)(t0 + ty*4+i)*DIi + tx*4) =
            make_float4(a2[i][0], a2[i][1], a2[i][2], a2[i][3]);

    float az[4][4], as_[4][4];
    #pragma unroll
    for (int i = 0; i < 4; i++)
        #pragma unroll
        for (int j = 0; j < 4; j++) { az[i][j]=0.f; as_[i][j]=0.f; }
    for (int u = 0; u < 64; u++) {
        float wz = sAe[u], ws = sEe[u];
        float aa[4], bb[4];
        #pragma unroll
        for (int j = 0; j < 4; j++) aa[j] = sv[u*65 + ty*4+j];
        #pragma unroll
        for (int j = 0; j < 4; j++) bb[j] = sk[u*65 + tx*4+j];
        #pragma unroll
        for (int i = 0; i < 4; i++) {
            float azw = wz*aa[i], asw = ws*aa[i];
            #pragma unroll
            for (int j = 0; j < 4; j++) { az[i][j] += azw*bb[j]; as_[i][j] += asw*bb[j]; }
        }
    }
    #pragma unroll
    for (int i = 0; i < 4; i++) {
        size_t go = (size_t)cc*4096 + (ty*4+i)*64 + tx*4;
        *(float4*)(g_gz + go) = make_float4(az[i][0], az[i][1], az[i][2], az[i][3]);
        *(float4*)(g_gs + go) = make_float4(as_[i][0], as_[i][1], as_[i][2], as_[i][3]);
    }
    if (tid < 128) g_sc[(size_t)cc*128 + tid] = ssc[tid];
    if (tid >= 128 && tid < 131) g_sc2[(size_t)cc*4 + (tid-128)] = ssc2[tid-128];
}

// ---------------- 4b. carry recurrence: scalar per-thread, 256 blocks -----
__global__ __launch_bounds__(256, 1)
void k_carry() {
    int idx = blockIdx.x * 256 + threadIdx.x;   // 0..65535
    int bh = idx >> 12, el = idx & 4095;
    size_t cc0 = (size_t)bh * 16;
    float S = 0.f, Z = 0.f;
    float gz = g_gz[cc0*4096 + el];
    float gs = g_gs[cc0*4096 + el];
    float a_ = g_sc2[cc0*4+0], d_ = g_sc2[cc0*4+1], f_ = g_sc2[cc0*4+2];
    #pragma unroll 4
    for (int c = 0; c < NC; c++) {
        size_t cc = cc0 + c;
        g_si[cc*4096 + el] = S;
        g_zi[cc*4096 + el] = Z;
        float ngz = 0.f, ngs = 0.f, na = 0.f, nd = 0.f, nf = 0.f;
        if (c + 1 < NC) {
            ngz = g_gz[(cc+1)*4096 + el];
            ngs = g_gs[(cc+1)*4096 + el];
            na = g_sc2[(cc+1)*4+0]; nd = g_sc2[(cc+1)*4+1]; nf = g_sc2[(cc+1)*4+2];
        }
        float Sn = d_*S - f_*Z + gs;
        Z = a_*Z - gz;
        S = Sn;
        gz = ngz; gs = ngs; a_ = na; d_ = nd; f_ = nf;
    }
}

// ---------------- 4c. cross terms: 240 blocks (skip c==0) -----------------
// y[t] += Dm(i-1) * (Q S_in^T) - F(i-1) * (Q Z_in^T)
__global__ __launch_bounds__(256, 1)
void k_cross() {
    extern __shared__ float smC[];
    float* sQ  = smC;           // 64x65
    float* sS  = smC + 4160;    // 64x65
    float* sZ  = smC + 8320;    // 64x65
    float* ssc = smC + 12480;   // 128
    int bh = blockIdx.x / 15;
    int c  = blockIdx.x - bh*15 + 1;   // 1..15
    int cc = bh*16 + c;
    int b = bh >> 3, h = bh & 7;
    int t0 = c * CS;
    const size_t base = (size_t)b * Nn * DIi + h * DHh;
    int tid = threadIdx.x;
    int lane = tid & 31, wid = tid >> 5;
    int g = lane >> 2, t4 = lane & 3;
    int wm = wid & 3, wn = wid >> 2;
    int i0 = wm * 16;
    int f4 = tid & 15, r0q = tid >> 4;

    #pragma unroll
    for (int rr = 0; rr < 4; rr++) {
        int row = rr*16 + r0q;
        float4 q = *(const float4*)(g_qp + base + (size_t)(t0+row)*DIi + f4*4);
        float4 s = *(const float4*)(g_si + (size_t)cc*4096 + row*64 + f4*4);
        float4 z = *(const float4*)(g_zi + (size_t)cc*4096 + row*64 + f4*4);
        int so = row*65 + f4*4;
        sQ[so]=q.x; sQ[so+1]=q.y; sQ[so+2]=q.z; sQ[so+3]=q.w;
        sS[so]=s.x; sS[so+1]=s.y; sS[so+2]=s.z; sS[so+3]=s.w;
        sZ[so]=z.x; sZ[so+1]=z.y; sZ[so+2]=z.z; sZ[so+3]=z.w;
    }
    if (tid < 128) ssc[tid] = g_sc[(size_t)cc*128 + tid];
    __syncthreads();

    float y1[4][4], y2[4][4];
    #pragma unroll
    for (int ni = 0; ni < 4; ni++)
        #pragma unroll
        for (int q = 0; q < 4; q++) { y1[ni][q] = 0.f; y2[ni][q] = 0.f; }

    #pragma unroll
    for (int k0 = 0; k0 < 64; k0 += 8) {
        unsigned a[4];
        a[0] = f2tf(sQ[(i0+g)*65   + k0+t4]);
        a[1] = f2tf(sQ[(i0+g+8)*65 + k0+t4]);
        a[2] = f2tf(sQ[(i0+g)*65   + k0+t4+4]);
        a[3] = f2tf(sQ[(i0+g+8)*65 + k0+t4+4]);
        #pragma unroll
        for (int ni = 0; ni < 4; ni++) {
            int r0 = wn*32 + ni*8;
            unsigned bs[2], bz[2];
            bs[0] = f2tf(sS[(r0+g)*65 + k0+t4]);
            bs[1] = f2tf(sS[(r0+g)*65 + k0+t4+4]);
            bz[0] = f2tf(sZ[(r0+g)*65 + k0+t4]);
            bz[1] = f2tf(sZ[(r0+g)*65 + k0+t4+4]);
            mma_tf32(y1[ni], a, bs);
            mma_tf32(y2[ni], a, bz);
        }
    }
    float dm0 = ssc[(i0+g)*2],     f0 = ssc[(i0+g)*2+1];
    float dm1 = ssc[(i0+g+8)*2],   f1 = ssc[(i0+g+8)*2+1];
    #pragma unroll
    for (int ni = 0; ni < 4; ni++) {
        int r0 = wn*32 + ni*8 + 2*t4;
        float* p0 = g_y + base + (size_t)(t0+i0+g)*DIi + r0;
        float* p1 = g_y + base + (size_t)(t0+i0+g+8)*DIi + r0;
        float2 e0 = *(float2*)p0, e1 = *(float2*)p1;
        e0.x += dm0*y1[ni][0] - f0*y2[ni][0];
        e0.y += dm0*y1[ni][1] - f0*y2[ni][1];
        e1.x += dm1*y1[ni][2] - f1*y2[ni][2];
        e1.y += dm1*y1[ni][3] - f1*y2[ni][3];
        *(float2*)p0 = e0; *(float2*)p1 = e1;
    }
}

// ---------------- launch ----------------
extern "C" void kernel_launch(void* const* d_in, const int* in_sizes, int n_in,
                              void* d_out, int out_size) {
    const float* x      = (const float*)d_in[0];
    const float* w_rms  = (const float*)d_in[1];
    const float* wq     = (const float*)d_in[2];
    const float* wk     = (const float*)d_in[3];
    const float* wv     = (const float*)d_in[4];
    const float* wo     = (const float*)d_in[5];
    const float* conv_q = (const float*)d_in[6];
    const float* conv_k = (const float*)d_in[7];
    const float* conv_v = (const float*)d_in[8];
    const float* gamma_q= (const float*)d_in[9];
    const float* gamma_k= (const float*)d_in[10];
    const float* lr_w   = (const float*)d_in[11];
    const float* lr_b   = (const float*)d_in[12];
    const float* decay_w= (const float*)d_in[13];
    const float* decay_b= (const float*)d_in[14];
    const float* mom_w  = (const float*)d_in[15];
    const float* mom_b  = (const float*)d_in[16];
    float* out = (float*)d_out;

    float *p_qp, *p_kp, *p_vp, *p_y;
    cudaGetSymbolAddress((void**)&p_qp, g_qp);
    cudaGetSymbolAddress((void**)&p_kp, g_kp);
    cudaGetSymbolAddress((void**)&p_vp, g_vp);
    cudaGetSymbolAddress((void**)&p_y,  g_y);

    int smG3 = 2*(2080 + 4*8*128) * (int)sizeof(unsigned);   // 49408
    int smG1 = 2*(2080 + 2*8*128) * (int)sizeof(unsigned);   // 33024
    int smA  = 17092 * (int)sizeof(float);
    int smC  = 12608 * (int)sizeof(float);                   // 50432
    cudaFuncSetAttribute(k_gemm3, cudaFuncAttributeMaxDynamicSharedMemorySize, smG3);
    cudaFuncSetAttribute(k_gemm1, cudaFuncAttributeMaxDynamicSharedMemorySize, smG1);
    cudaFuncSetAttribute(k_chunkA, cudaFuncAttributeMaxDynamicSharedMemorySize, smA);
    cudaFuncSetAttribute(k_cross, cudaFuncAttributeMaxDynamicSharedMemorySize, smC);

    k_rmsnorm<<<BN, 256>>>(x, w_rms);
    dim3 gqkv(DIi/256, BN/128, 4);   // z<3: QKV GEMM, z==3: gates
    k_gemm3<<<gqkv, 256, smG3>>>(wq, wk, wv, conv_q, conv_k, conv_v,
                                 lr_w, decay_w, mom_w, p_qp, p_kp, p_vp);
    k_chunkA<<<256, 256, smA>>>(lr_b, decay_b, mom_b, gamma_q, gamma_k);
    k_carry<<<256, 256>>>();
    k_cross<<<240, 256, smC>>>();
    dim3 gout(DIMM/128, BN/128);
    k_gemm1<<<gout, 256, smG1>>>(p_y, wo, out, DIMM, DIi);
}